// round 1
// baseline (speedup 1.0000x reference)
#include <cuda_runtime.h>
#include <cuda_bf16.h>
#include <cstdint>

#define NMAX 20000
#define EMAX 320000
#define ETOT_MAX (EMAX + NMAX)
#define HID 256
#define HEADS 8

// ---------------- scratch (device globals; no allocation) ----------------
__device__ float g_h1[NMAX * HID];
__device__ float g_h2[NMAX * HID];
__device__ float g_xmlp[NMAX * HID];
__device__ float g_g[NMAX * HID];
__device__ float g_xl[NMAX * HID];
__device__ float g_xr[NMAX * HID];
__device__ float g_agg[NMAX * HID];
__device__ float g_logits[ETOT_MAX * HEADS];
__device__ float g_aexp[ETOT_MAX * HEADS];
__device__ unsigned g_mmax[NMAX * HEADS];
__device__ float g_ssum[NMAX * HEADS];
__device__ float g_xc[NMAX * 2 * HID];
__device__ float g_t1[NMAX * HID];
__device__ float g_t2[NMAX * 128];
__device__ float g_t3[NMAX * 64];

// ---------------- generic tiled fp32 GEMM, 64x64 tile --------------------
// C[M,Nc] = act( bn( A[M,K] @ B[K,Nc] + bias ) )
// mode: 0 = bias only, 1 = bias + BN(eval) + lrelu(0.1), 2 = bias + lrelu(0.1)
__global__ void gemm64_kernel(const float* __restrict__ A,
                              const float* __restrict__ B,
                              const float* __restrict__ bias,
                              const float* __restrict__ bn_g,
                              const float* __restrict__ bn_b,
                              float* __restrict__ C,
                              int M, int Nc, int K, int mode)
{
    __shared__ float As[16][68];
    __shared__ float Bs[16][68];
    const int tid = threadIdx.x;
    const int m0 = blockIdx.y * 64;
    const int n0 = blockIdx.x * 64;
    const int tx = tid & 15;
    const int ty = tid >> 4;

    float acc[4][4] = {};

    const int a_mm = tid >> 2;          // 0..63 (row within tile)
    const int a_q  = (tid & 3) * 4;     // 0,4,8,12 (k offset)
    const int b_kk = tid >> 4;          // 0..15
    const int b_q  = (tid & 15) * 4;    // 0..60

    for (int k0 = 0; k0 < K; k0 += 16) {
        float4 av = make_float4(0.f, 0.f, 0.f, 0.f);
        int arow = m0 + a_mm;
        if (arow < M)
            av = *reinterpret_cast<const float4*>(A + (size_t)arow * K + k0 + a_q);
        As[a_q + 0][a_mm] = av.x;
        As[a_q + 1][a_mm] = av.y;
        As[a_q + 2][a_mm] = av.z;
        As[a_q + 3][a_mm] = av.w;

        float4 bv = *reinterpret_cast<const float4*>(B + (size_t)(k0 + b_kk) * Nc + n0 + b_q);
        *reinterpret_cast<float4*>(&Bs[b_kk][b_q]) = bv;
        __syncthreads();

        #pragma unroll
        for (int kk = 0; kk < 16; kk++) {
            float4 ar = *reinterpret_cast<const float4*>(&As[kk][ty * 4]);
            float4 br = *reinterpret_cast<const float4*>(&Bs[kk][tx * 4]);
            float a_[4] = {ar.x, ar.y, ar.z, ar.w};
            float b_[4] = {br.x, br.y, br.z, br.w};
            #pragma unroll
            for (int i = 0; i < 4; i++)
                #pragma unroll
                for (int j = 0; j < 4; j++)
                    acc[i][j] = fmaf(a_[i], b_[j], acc[i][j]);
        }
        __syncthreads();
    }

    #pragma unroll
    for (int j = 0; j < 4; j++) {
        int col = n0 + tx * 4 + j;
        float bs = bias ? bias[col] : 0.f;
        float sc = 1.f, sh = 0.f;
        if (mode == 1) { sc = bn_g[col] * rsqrtf(1.f + 1e-5f); sh = bn_b[col]; }
        #pragma unroll
        for (int i = 0; i < 4; i++) {
            int row = m0 + ty * 4 + i;
            if (row < M) {
                float v = acc[i][j] + bs;
                if (mode == 1) { v = v * sc + sh; v = v > 0.f ? v : 0.1f * v; }
                else if (mode == 2) { v = v > 0.f ? v : 0.1f * v; }
                C[(size_t)row * Nc + col] = v;
            }
        }
    }
}

// ---------------- per-layer init: agg=bias, mmax=0(enc -inf), ssum=0 -------
__global__ void init_layer_kernel(float* __restrict__ agg,
                                  const float* __restrict__ bias,
                                  unsigned* __restrict__ mmax,
                                  float* __restrict__ ssum, int N)
{
    int i = blockIdx.x * blockDim.x + threadIdx.x;
    if (i < N * HID) agg[i] = bias[i & (HID - 1)];
    if (i < N * HEADS) { mmax[i] = 0u; ssum[i] = 0.f; }
}

// ---------------- edge pass A: logits + segment max -----------------------
__global__ void edge_logits_kernel(const float* __restrict__ xl,
                                   const float* __restrict__ xr,
                                   const int* __restrict__ ei,
                                   const float* __restrict__ att,
                                   float* __restrict__ logits,
                                   unsigned* __restrict__ mmax,
                                   int E, int N)
{
    int warp = (blockIdx.x * blockDim.x + threadIdx.x) >> 5;
    int lane = threadIdx.x & 31;
    int Et = E + N;
    if (warp >= Et) return;
    int s, d;
    if (warp < E) { s = ei[warp]; d = ei[E + warp]; }
    else          { s = d = warp - E; }

    const float4* xs = (const float4*)(xl + (size_t)s * HID);
    const float4* xd = (const float4*)(xr + (size_t)d * HID);
    const float4* at = (const float4*)att;

    float p[2];
    #pragma unroll
    for (int it = 0; it < 2; it++) {
        float4 a = xs[it * 32 + lane];
        float4 b = xd[it * 32 + lane];
        float4 w = at[it * 32 + lane];
        float v0 = a.x + b.x; v0 = v0 > 0.f ? v0 : 0.2f * v0;
        float v1 = a.y + b.y; v1 = v1 > 0.f ? v1 : 0.2f * v1;
        float v2 = a.z + b.z; v2 = v2 > 0.f ? v2 : 0.2f * v2;
        float v3 = a.w + b.w; v3 = v3 > 0.f ? v3 : 0.2f * v3;
        float pp = v0 * w.x + v1 * w.y + v2 * w.z + v3 * w.w;
        // reduce within 8-lane groups (one head per group per iteration)
        pp += __shfl_xor_sync(0xffffffffu, pp, 4);
        pp += __shfl_xor_sync(0xffffffffu, pp, 2);
        pp += __shfl_xor_sync(0xffffffffu, pp, 1);
        p[it] = pp;
    }
    // group-leader lanes {0,8,16,24} hold heads {it*4 + lane/8}
    float v0 = __shfl_sync(0xffffffffu, p[0], (lane & 3) * 8);
    float v1 = __shfl_sync(0xffffffffu, p[1], (lane & 3) * 8);
    if (lane < 8) {
        float v = (lane < 4) ? v0 : v1;
        logits[(size_t)warp * 8 + lane] = v;
        unsigned key = __float_as_uint(v);
        key = (key & 0x80000000u) ? ~key : (key | 0x80000000u);
        atomicMax(&mmax[d * 8 + lane], key);
    }
}

// ---------------- edge pass B: a = exp(logit - m), segment sum ------------
__global__ void edge_exp_kernel(const float* __restrict__ logits,
                                const unsigned* __restrict__ mmax,
                                const int* __restrict__ ei,
                                float* __restrict__ aexp,
                                float* __restrict__ ssum,
                                int E, int N)
{
    int e = blockIdx.x * blockDim.x + threadIdx.x;
    int Et = E + N;
    if (e >= Et) return;
    int d = (e < E) ? ei[E + e] : (e - E);
    #pragma unroll
    for (int h = 0; h < 8; h++) {
        unsigned key = mmax[d * 8 + h];
        unsigned bits = (key & 0x80000000u) ? (key ^ 0x80000000u) : ~key;
        float m = __uint_as_float(bits);
        float a = expf(logits[(size_t)e * 8 + h] - m);
        aexp[(size_t)e * 8 + h] = a;
        atomicAdd(&ssum[d * 8 + h], a);
    }
}

// ---------------- edge pass C: out[dst] += xl[src] * alpha ---------------
__global__ void edge_aggr_kernel(const float* __restrict__ xl,
                                 const float* __restrict__ aexp,
                                 const float* __restrict__ ssum,
                                 const int* __restrict__ ei,
                                 float* __restrict__ agg,
                                 int E, int N)
{
    int warp = (blockIdx.x * blockDim.x + threadIdx.x) >> 5;
    int lane = threadIdx.x & 31;
    int Et = E + N;
    if (warp >= Et) return;
    int s, d;
    if (warp < E) { s = ei[warp]; d = ei[E + warp]; }
    else          { s = d = warp - E; }

    float alpha = 0.f;
    if (lane < 8)
        alpha = aexp[(size_t)warp * 8 + lane] / (ssum[d * 8 + lane] + 1e-16f);

    const float4* xs = (const float4*)(xl + (size_t)s * HID);
    float4* od = (float4*)(agg + (size_t)d * HID);
    #pragma unroll
    for (int it = 0; it < 2; it++) {
        float al = __shfl_sync(0xffffffffu, alpha, it * 4 + (lane >> 3));
        float4 v = xs[it * 32 + lane];
        v.x *= al; v.y *= al; v.z *= al; v.w *= al;
        atomicAdd(&od[it * 32 + lane], v);   // sm_90+ vector atomic
    }
}

// ---------------- per-node: LayerNorm + lrelu + residual ------------------
__global__ void node_ln_kernel(const float* __restrict__ agg,
                               const float* __restrict__ lng,
                               const float* __restrict__ lnb,
                               float* __restrict__ g, int N)
{
    int warp = (blockIdx.x * blockDim.x + threadIdx.x) >> 5;
    int lane = threadIdx.x & 31;
    if (warp >= N) return;
    const float* row = agg + (size_t)warp * HID;
    float v[8];
    float s = 0.f;
    #pragma unroll
    for (int i = 0; i < 8; i++) { v[i] = row[i * 32 + lane]; s += v[i]; }
    #pragma unroll
    for (int o = 16; o; o >>= 1) s += __shfl_xor_sync(0xffffffffu, s, o);
    float mu = s * (1.f / 256.f);
    float var = 0.f;
    #pragma unroll
    for (int i = 0; i < 8; i++) { float dd = v[i] - mu; var += dd * dd; }
    #pragma unroll
    for (int o = 16; o; o >>= 1) var += __shfl_xor_sync(0xffffffffu, var, o);
    var *= (1.f / 256.f);
    float inv = rsqrtf(var + 1e-5f);
    #pragma unroll
    for (int i = 0; i < 8; i++) {
        int j = i * 32 + lane;
        float o_ = (v[i] - mu) * inv * lng[j] + lnb[j];
        o_ = o_ > 0.f ? o_ : 0.1f * o_;
        g[(size_t)warp * HID + j] += o_;   // residual: g = res + o
    }
}

// ---------------- concat [xmlp | g] --------------------------------------
__global__ void concat_kernel(const float* __restrict__ a,
                              const float* __restrict__ b,
                              float* __restrict__ xc, int N)
{
    int i = blockIdx.x * blockDim.x + threadIdx.x;
    if (i >= N * 512) return;
    int n = i >> 9, j = i & 511;
    xc[i] = (j < 256) ? a[(size_t)n * 256 + j] : b[(size_t)n * 256 + j - 256];
}

// ---------------- final head: out = t3 @ w4 + b4 -------------------------
__global__ void head_final_kernel(const float* __restrict__ t3,
                                  const float* __restrict__ w4,
                                  const float* __restrict__ b4,
                                  float* __restrict__ out, int N)
{
    int warp = (blockIdx.x * blockDim.x + threadIdx.x) >> 5;
    int lane = threadIdx.x & 31;
    if (warp >= N) return;
    const float* r = t3 + (size_t)warp * 64;
    float acc = r[lane] * w4[lane] + r[lane + 32] * w4[lane + 32];
    #pragma unroll
    for (int o = 16; o; o >>= 1) acc += __shfl_xor_sync(0xffffffffu, acc, o);
    if (lane == 0) out[warp] = acc + b4[0];
}

// =========================================================================
extern "C" void kernel_launch(void* const* d_in, const int* in_sizes, int n_in,
                              void* d_out, int out_size)
{
    const float* x       = (const float*)d_in[0];
    const int*   ei      = (const int*)  d_in[1];
    const float* mlp_w1  = (const float*)d_in[2];
    const float* mlp_b1  = (const float*)d_in[3];
    const float* bn1_g   = (const float*)d_in[4];
    const float* bn1_b   = (const float*)d_in[5];
    const float* mlp_w2  = (const float*)d_in[6];
    const float* mlp_b2  = (const float*)d_in[7];
    const float* bn2_g   = (const float*)d_in[8];
    const float* bn2_b   = (const float*)d_in[9];
    const float* mlp_w3  = (const float*)d_in[10];
    const float* mlp_b3  = (const float*)d_in[11];
    const float* gat_wl  = (const float*)d_in[12];
    const float* gat_bl  = (const float*)d_in[13];
    const float* gat_wr  = (const float*)d_in[14];
    const float* gat_br  = (const float*)d_in[15];
    const float* gat_att = (const float*)d_in[16];
    const float* gat_bias= (const float*)d_in[17];
    const float* ln_g    = (const float*)d_in[18];
    const float* ln_b    = (const float*)d_in[19];
    const float* head_w1 = (const float*)d_in[20];
    const float* head_b1 = (const float*)d_in[21];
    const float* hbn1_g  = (const float*)d_in[22];
    const float* hbn1_b  = (const float*)d_in[23];
    const float* head_w2 = (const float*)d_in[24];
    const float* head_b2 = (const float*)d_in[25];
    const float* hbn2_g  = (const float*)d_in[26];
    const float* hbn2_b  = (const float*)d_in[27];
    const float* head_w3 = (const float*)d_in[28];
    const float* head_b3 = (const float*)d_in[29];
    const float* head_w4 = (const float*)d_in[30];
    const float* head_b4 = (const float*)d_in[31];

    int N = in_sizes[0] / 128;
    int E = in_sizes[1] / 2;
    if (N > NMAX) N = NMAX;
    if (E > EMAX) E = EMAX;
    int Et = E + N;

    float *h1, *h2, *xmlp, *g, *xl, *xr, *agg, *logits, *aexp, *ssum, *xc, *t1, *t2, *t3;
    unsigned* mmax;
    cudaGetSymbolAddress((void**)&h1,     g_h1);
    cudaGetSymbolAddress((void**)&h2,     g_h2);
    cudaGetSymbolAddress((void**)&xmlp,   g_xmlp);
    cudaGetSymbolAddress((void**)&g,      g_g);
    cudaGetSymbolAddress((void**)&xl,     g_xl);
    cudaGetSymbolAddress((void**)&xr,     g_xr);
    cudaGetSymbolAddress((void**)&agg,    g_agg);
    cudaGetSymbolAddress((void**)&logits, g_logits);
    cudaGetSymbolAddress((void**)&aexp,   g_aexp);
    cudaGetSymbolAddress((void**)&mmax,   g_mmax);
    cudaGetSymbolAddress((void**)&ssum,   g_ssum);
    cudaGetSymbolAddress((void**)&xc,     g_xc);
    cudaGetSymbolAddress((void**)&t1,     g_t1);
    cudaGetSymbolAddress((void**)&t2,     g_t2);
    cudaGetSymbolAddress((void**)&t3,     g_t3);

    dim3 blk(256);
    auto ggrid = [](int M, int Nc) { return dim3((unsigned)((Nc + 63) / 64), (unsigned)((M + 63) / 64)); };

    // Feature MLP
    gemm64_kernel<<<ggrid(N, 256), blk>>>(x,  mlp_w1, mlp_b1, bn1_g, bn1_b, h1,   N, 256, 128, 1);
    gemm64_kernel<<<ggrid(N, 256), blk>>>(h1, mlp_w2, mlp_b2, bn2_g, bn2_b, h2,   N, 256, 256, 1);
    gemm64_kernel<<<ggrid(N, 256), blk>>>(h2, mlp_w3, mlp_b3, nullptr, nullptr, xmlp, N, 256, 256, 0);

    cudaMemcpyAsync(g, xmlp, (size_t)N * HID * sizeof(float), cudaMemcpyDeviceToDevice);

    int eb_warp = (Et * 32 + 255) / 256;  // warp-per-edge grids
    int eb_thr  = (Et + 255) / 256;

    for (int l = 0; l < 4; l++) {
        const float* wl  = gat_wl  + (size_t)l * 256 * 256;
        const float* bl  = gat_bl  + (size_t)l * 256;
        const float* wr  = gat_wr  + (size_t)l * 256 * 256;
        const float* br  = gat_br  + (size_t)l * 256;
        const float* at  = gat_att + (size_t)l * 256;
        const float* gb  = gat_bias+ (size_t)l * 256;
        const float* lg  = ln_g    + (size_t)l * 256;
        const float* lb  = ln_b    + (size_t)l * 256;

        gemm64_kernel<<<ggrid(N, 256), blk>>>(g, wl, bl, nullptr, nullptr, xl, N, 256, 256, 0);
        gemm64_kernel<<<ggrid(N, 256), blk>>>(g, wr, br, nullptr, nullptr, xr, N, 256, 256, 0);

        init_layer_kernel<<<(N * 256 + 255) / 256, blk>>>(agg, gb, mmax, ssum, N);
        edge_logits_kernel<<<eb_warp, blk>>>(xl, xr, ei, at, logits, mmax, E, N);
        edge_exp_kernel<<<eb_thr, blk>>>(logits, mmax, ei, aexp, ssum, E, N);
        edge_aggr_kernel<<<eb_warp, blk>>>(xl, aexp, ssum, ei, agg, E, N);
        node_ln_kernel<<<(N * 32 + 255) / 256, blk>>>(agg, lg, lb, g, N);
    }

    // head
    concat_kernel<<<(N * 512 + 255) / 256, blk>>>(xmlp, g, xc, N);
    gemm64_kernel<<<ggrid(N, 256), blk>>>(xc, head_w1, head_b1, hbn1_g, hbn1_b, t1, N, 256, 512, 1);
    gemm64_kernel<<<ggrid(N, 128), blk>>>(t1, head_w2, head_b2, hbn2_g, hbn2_b, t2, N, 128, 256, 1);
    gemm64_kernel<<<ggrid(N,  64), blk>>>(t2, head_w3, head_b3, nullptr, nullptr, t3, N, 64, 128, 2);
    head_final_kernel<<<(N * 32 + 255) / 256, blk>>>(t3, head_w4, head_b4, (float*)d_out, N);
}